// round 13
// baseline (speedup 1.0000x reference)
#include <cuda_runtime.h>
#include <cuda_bf16.h>
#include <cstdint>

// NVAR feature expansion:
//   X: (8, 4, 4096) f32  ->  out: (8, 4, 3996, 231) f32
//   features per (b,r,t): [1, tap_0..tap_9, 220 degree-3 monomials (i<=j<=k)]
//   tap_k = X[b, r, t + 2k - 18], t = tout + 100  (always in-bounds)

#define KTAPS   10
#define NMON    220
#define NF      231                 // 1 + KTAPS + NMON
#define NT_IN   4096
#define TRANS   100
#define NT_OUT  (NT_IN - TRANS)     // 3996
#define PADL    18                  // (KTAPS-1)*SKIP
#define TILE_T  32
#define NTHREADS 256
#define TPB      5                  // tiles per block (125 = 25 * 5)
#define TILE_WORDS (TILE_T * NF)    // 7392 floats = 29568 B
#define TILE_F4    (TILE_WORDS / 4) // 1848 float4
#define SMEM_BYTES (2 * TILE_WORDS * 4)   // 59136 B (double buffer)

// Per-group feature ranges over [0, 231): groups 0..6 get 29, group 7 gets 28.
template <int G>
__device__ __forceinline__ void do_feats(const float (&x)[KTAPS], float* __restrict__ srow) {
    constexpr int LO = G * 29;
    constexpr int HI = (G == 7) ? NF : LO + 29;

    if (LO == 0) srow[0] = 1.0f;

    #pragma unroll
    for (int t = 0; t < KTAPS; ++t)
        if (t + 1 >= LO && t + 1 < HI) srow[t + 1] = x[t];

    // monomials in lexicographic (a<=b<=c) order; product ((xa*xb)*xc) == jnp.prod order
    int m = 0;
    #pragma unroll
    for (int a = 0; a < KTAPS; ++a) {
        #pragma unroll
        for (int b = a; b < KTAPS; ++b) {
            float xab = x[a] * x[b];            // DCE'd when no store lands in [LO,HI)
            #pragma unroll
            for (int c = b; c < KTAPS; ++c) {
                int f = 1 + KTAPS + m;
                if (f >= LO && f < HI) srow[f] = xab * x[c];
                ++m;
            }
        }
    }
}

__device__ __forceinline__ void compute_tile(const float* __restrict__ Xtap, int t0,
                                             int valid, int tl, int g,
                                             float* __restrict__ buf) {
    if (tl < valid) {
        float x[KTAPS];
        #pragma unroll
        for (int t = 0; t < KTAPS; ++t)
            x[t] = __ldg(Xtap + t0 + 2 * t);             // L1-hot, coalesced per warp

        float* srow = buf + tl * NF;            // stride 231 words -> 32 distinct banks
        switch (g) {                            // warp-uniform, no divergence
            case 0: do_feats<0>(x, srow); break;
            case 1: do_feats<1>(x, srow); break;
            case 2: do_feats<2>(x, srow); break;
            case 3: do_feats<3>(x, srow); break;
            case 4: do_feats<4>(x, srow); break;
            case 5: do_feats<5>(x, srow); break;
            case 6: do_feats<6>(x, srow); break;
            default: do_feats<7>(x, srow); break;
        }
    }
}

__global__ __launch_bounds__(NTHREADS)
void nvar_kernel(const float* __restrict__ X, float* __restrict__ out) {
    extern __shared__ float s_buf[];            // 2 buffers, layout == global rows

    const int tid  = threadIdx.x;
    const int tl   = tid & (TILE_T - 1);        // time-step within tile (0..31)
    const int g    = tid >> 5;                  // warp id = feature group (0..7)
    const int br   = blockIdx.y;                // b*4 + r, 0..31
    const int base = blockIdx.x * (TPB * TILE_T);

    const float* Xtap = X + (size_t)br * NT_IN + (TRANS - PADL) + tl;
    float*       gout = out + (size_t)br * NT_OUT * NF;

    #pragma unroll
    for (int ti = 0; ti < TPB; ++ti) {
        const int t0    = base + ti * TILE_T;
        const int valid = min(TILE_T, NT_OUT - t0);      // partial only on very last tile
        float* cur = s_buf + (ti & 1) * TILE_WORDS;

        // 1) issue drain loads of PREVIOUS tile first (29-cyc LDS hidden under compute)
        float4 w0, w1, w2, w3, w4, w5, w6, w7;
        if (ti > 0) {
            const float4* p4 = reinterpret_cast<const float4*>(
                s_buf + ((ti - 1) & 1) * TILE_WORDS);
            w0 = p4[tid];            w1 = p4[tid + 1 * NTHREADS];
            w2 = p4[tid + 2 * NTHREADS]; w3 = p4[tid + 3 * NTHREADS];
            w4 = p4[tid + 4 * NTHREADS]; w5 = p4[tid + 5 * NTHREADS];
            w6 = p4[tid + 6 * NTHREADS];
            if (tid < TILE_F4 - 7 * NTHREADS) w7 = p4[tid + 7 * NTHREADS];
        }

        // 2) compute current tile (LDG taps + FMUL + STS) — independent of the LDS above
        compute_tile(Xtap, t0, valid, tl, g, cur);

        // 3) stream previous tile to global (fire-and-forget, .cs keeps L2 from thrashing)
        if (ti > 0) {
            float4* g4 = reinterpret_cast<float4*>(gout + (size_t)(t0 - TILE_T) * NF);
            __stcs(g4 + tid,                w0);
            __stcs(g4 + tid + 1 * NTHREADS, w1);
            __stcs(g4 + tid + 2 * NTHREADS, w2);
            __stcs(g4 + tid + 3 * NTHREADS, w3);
            __stcs(g4 + tid + 4 * NTHREADS, w4);
            __stcs(g4 + tid + 5 * NTHREADS, w5);
            __stcs(g4 + tid + 6 * NTHREADS, w6);
            if (tid < TILE_F4 - 7 * NTHREADS)
                __stcs(g4 + tid + 7 * NTHREADS, w7);
        }

        // one barrier per tile: publishes cur's STS for next drain AND protects
        // buffer reuse (drain LDS of buf B in iter i vs STS to buf B in iter i+2).
        __syncthreads();
    }

    // epilogue: drain the last tile (buffer (TPB-1)&1)
    {
        const int t0l    = base + (TPB - 1) * TILE_T;
        const int validl = min(TILE_T, NT_OUT - t0l);
        const float4* s4 = reinterpret_cast<const float4*>(
            s_buf + ((TPB - 1) & 1) * TILE_WORDS);
        float4* g4 = reinterpret_cast<float4*>(gout + (size_t)t0l * NF);

        if (validl == TILE_T) {
            float4 v0 = s4[tid];            float4 v1 = s4[tid + 1 * NTHREADS];
            float4 v2 = s4[tid + 2 * NTHREADS]; float4 v3 = s4[tid + 3 * NTHREADS];
            float4 v4 = s4[tid + 4 * NTHREADS]; float4 v5 = s4[tid + 5 * NTHREADS];
            float4 v6 = s4[tid + 6 * NTHREADS];
            __stcs(g4 + tid,                v0);
            __stcs(g4 + tid + 1 * NTHREADS, v1);
            __stcs(g4 + tid + 2 * NTHREADS, v2);
            __stcs(g4 + tid + 3 * NTHREADS, v3);
            __stcs(g4 + tid + 4 * NTHREADS, v4);
            __stcs(g4 + tid + 5 * NTHREADS, v5);
            __stcs(g4 + tid + 6 * NTHREADS, v6);
            if (tid < TILE_F4 - 7 * NTHREADS)
                __stcs(g4 + tid + 7 * NTHREADS, s4[tid + 7 * NTHREADS]);
        } else {
            const int n4 = (validl * NF) >> 2;           // 1617 on the single partial tile
            #pragma unroll 4
            for (int i = tid; i < n4; i += NTHREADS)
                __stcs(g4 + i, s4[i]);
        }
    }
}

extern "C" void kernel_launch(void* const* d_in, const int* in_sizes, int n_in,
                              void* d_out, int out_size) {
    const float* X   = (const float*)d_in[0];
    float*       out = (float*)d_out;

    cudaFuncSetAttribute(nvar_kernel, cudaFuncAttributeMaxDynamicSharedMemorySize,
                         SMEM_BYTES);

    const int br_total = in_sizes[0] / NT_IN;                 // 32
    const int tiles    = (NT_OUT + TILE_T - 1) / TILE_T;      // 125
    dim3 grid((tiles + TPB - 1) / TPB, br_total);             // 25 x 32 = 800 blocks
    nvar_kernel<<<grid, NTHREADS, SMEM_BYTES>>>(X, out);
}

// round 14
// speedup vs baseline: 1.0784x; 1.0784x over previous
#include <cuda_runtime.h>
#include <cuda_bf16.h>
#include <cstdint>

// NVAR feature expansion:
//   X: (8, 4, 4096) f32  ->  out: (8, 4, 3996, 231) f32
//   features per (b,r,t): [1, tap_0..tap_9, 220 degree-3 monomials (i<=j<=k)]
//   tap_k = X[b, r, t + 2k - 18], t = tout + 100  (always in-bounds)

#define KTAPS   10
#define NMON    220
#define NF      231                 // 1 + KTAPS + NMON
#define NT_IN   4096
#define TRANS   100
#define NT_OUT  (NT_IN - TRANS)     // 3996
#define PADL    18                  // (KTAPS-1)*SKIP
#define TILE_T  32
#define NCOMP   256                 // compute threads (8 warps, one per feature group)
#define NTHREADS 384                // + 4 drain-only warps
#define TILE_F4  ((TILE_T * NF) / 4)   // 1848 float4 per tile

// Per-group feature ranges over [0, 231): groups 0..6 get 29, group 7 gets 28.
template <int G>
__device__ __forceinline__ void do_feats(const float (&x)[KTAPS], float* __restrict__ srow) {
    constexpr int LO = G * 29;
    constexpr int HI = (G == 7) ? NF : LO + 29;

    if (LO == 0) srow[0] = 1.0f;

    #pragma unroll
    for (int t = 0; t < KTAPS; ++t)
        if (t + 1 >= LO && t + 1 < HI) srow[t + 1] = x[t];

    // monomials in lexicographic (a<=b<=c) order; product ((xa*xb)*xc) == jnp.prod order
    int m = 0;
    #pragma unroll
    for (int a = 0; a < KTAPS; ++a) {
        #pragma unroll
        for (int b = a; b < KTAPS; ++b) {
            float xab = x[a] * x[b];            // DCE'd when no store lands in [LO,HI)
            #pragma unroll
            for (int c = b; c < KTAPS; ++c) {
                int f = 1 + KTAPS + m;
                if (f >= LO && f < HI) srow[f] = xab * x[c];
                ++m;
            }
        }
    }
}

__global__ __launch_bounds__(NTHREADS)
void nvar_kernel(const float* __restrict__ X, float* __restrict__ out) {
    __shared__ alignas(16) float s_out[TILE_T * NF];    // 29568 B, layout == global rows

    const int tid   = threadIdx.x;
    const int br    = blockIdx.y;               // b*4 + r, 0..31
    const int t0    = blockIdx.x * TILE_T;
    const int valid = min(TILE_T, NT_OUT - t0); // 32, or 28 on the last tile

    // ---- compute phase: warps 0..7 only (identical to best kernel) ----
    if (tid < NCOMP) {
        const int tl = tid & (TILE_T - 1);      // time-step within tile (0..31)
        const int g  = tid >> 5;                // warp id = feature group (0..7)
        if (tl < valid) {
            const float* Xtap = X + (size_t)br * NT_IN + (TRANS - PADL) + t0 + tl;
            float x[KTAPS];
            #pragma unroll
            for (int t = 0; t < KTAPS; ++t)
                x[t] = __ldg(Xtap + 2 * t);              // L1-hot, coalesced per warp

            float* srow = s_out + tl * NF;      // stride 231 words -> 32 distinct banks
            switch (g) {                        // warp-uniform, no divergence
                case 0: do_feats<0>(x, srow); break;
                case 1: do_feats<1>(x, srow); break;
                case 2: do_feats<2>(x, srow); break;
                case 3: do_feats<3>(x, srow); break;
                case 4: do_feats<4>(x, srow); break;
                case 5: do_feats<5>(x, srow); break;
                case 6: do_feats<6>(x, srow); break;
                default: do_feats<7>(x, srow); break;
            }
        }
    }
    __syncthreads();

    // ---- drain phase: all 12 warps. Tile is a flat run of valid*NF floats;
    // global base (br*3996 + t0)*231*4 B is 16B-aligned (3996%4==0, t0%4==0).
    // __stcs: streaming stores, keeps 118MB output from thrashing L2 (proven win).
    const float4* s4 = reinterpret_cast<const float4*>(s_out);
    float4* g4 = reinterpret_cast<float4*>(out + ((size_t)br * NT_OUT + t0) * NF);

    if (valid == TILE_T) {
        // 1848 = 4*384 + 312: 4 unrolled iters + predicated tail
        float4 v0 = s4[tid + 0 * NTHREADS];
        float4 v1 = s4[tid + 1 * NTHREADS];
        float4 v2 = s4[tid + 2 * NTHREADS];
        float4 v3 = s4[tid + 3 * NTHREADS];
        __stcs(g4 + tid + 0 * NTHREADS, v0);
        __stcs(g4 + tid + 1 * NTHREADS, v1);
        __stcs(g4 + tid + 2 * NTHREADS, v2);
        __stcs(g4 + tid + 3 * NTHREADS, v3);
        if (tid < TILE_F4 - 4 * NTHREADS)       // 312 remainder float4s
            __stcs(g4 + tid + 4 * NTHREADS, s4[tid + 4 * NTHREADS]);
    } else {
        const int n4 = (valid * NF) >> 2;       // 1617 on the single partial tile
        #pragma unroll 4
        for (int i = tid; i < n4; i += NTHREADS)
            __stcs(g4 + i, s4[i]);
    }
}

extern "C" void kernel_launch(void* const* d_in, const int* in_sizes, int n_in,
                              void* d_out, int out_size) {
    const float* X   = (const float*)d_in[0];
    float*       out = (float*)d_out;

    const int br_total = in_sizes[0] / NT_IN;                 // 32
    dim3 grid((NT_OUT + TILE_T - 1) / TILE_T, br_total);      // 125 x 32 = 4000 blocks
    nvar_kernel<<<grid, NTHREADS>>>(X, out);
}

// round 15
// speedup vs baseline: 1.1807x; 1.0949x over previous
#include <cuda_runtime.h>
#include <cuda_bf16.h>
#include <cstdint>

// NVAR feature expansion:
//   X: (8, 4, 4096) f32  ->  out: (8, 4, 3996, 231) f32
//   features per (b,r,t): [1, tap_0..tap_9, 220 degree-3 monomials (i<=j<=k)]
//   tap_k = X[b, r, t + 2k - 18], t = tout + 100  (always in-bounds)

#define KTAPS   10
#define NMON    220
#define NF      231                 // 1 + KTAPS + NMON
#define NT_IN   4096
#define TRANS   100
#define NT_OUT  (NT_IN - TRANS)     // 3996
#define PADL    18                  // (KTAPS-1)*SKIP
#define TILE_T  32
#define NTHREADS 256

// Per-group feature ranges over [0, 231): groups 0..6 get 29, group 7 gets 28.
template <int G>
__device__ __forceinline__ void do_feats(const float (&x)[KTAPS], float* __restrict__ srow) {
    constexpr int LO = G * 29;
    constexpr int HI = (G == 7) ? NF : LO + 29;

    if (LO == 0) srow[0] = 1.0f;

    #pragma unroll
    for (int t = 0; t < KTAPS; ++t)
        if (t + 1 >= LO && t + 1 < HI) srow[t + 1] = x[t];

    // monomials in lexicographic (a<=b<=c) order; product ((xa*xb)*xc) == jnp.prod order
    int m = 0;
    #pragma unroll
    for (int a = 0; a < KTAPS; ++a) {
        #pragma unroll
        for (int b = a; b < KTAPS; ++b) {
            float xab = x[a] * x[b];            // DCE'd when no store lands in [LO,HI)
            #pragma unroll
            for (int c = b; c < KTAPS; ++c) {
                int f = 1 + KTAPS + m;
                if (f >= LO && f < HI) srow[f] = xab * x[c];
                ++m;
            }
        }
    }
}

__device__ __forceinline__ uint32_t smem_u32(const void* p) {
    uint32_t a;
    asm("{ .reg .u64 t; cvta.to.shared.u64 t, %1; cvt.u32.u64 %0, t; }" : "=r"(a) : "l"(p));
    return a;
}

__global__ __launch_bounds__(NTHREADS)
void nvar_kernel(const float* __restrict__ X, float* __restrict__ out) {
    __shared__ alignas(16) float s_out[TILE_T * NF];    // 29568 B, layout == global rows

    const int tid   = threadIdx.x;
    const int tl    = tid & (TILE_T - 1);       // time-step within tile (0..31)
    const int g     = tid >> 5;                 // warp id = feature group (0..7)
    const int br    = blockIdx.y;               // b*4 + r, 0..31
    const int t0    = blockIdx.x * TILE_T;
    const int valid = min(TILE_T, NT_OUT - t0); // 32, or 28 on the last tile

    if (tl < valid) {
        const float* Xtap = X + (size_t)br * NT_IN + (TRANS - PADL) + t0 + tl;
        float x[KTAPS];
        #pragma unroll
        for (int t = 0; t < KTAPS; ++t)
            x[t] = __ldg(Xtap + 2 * t);                  // L1-hot, coalesced per warp

        float* srow = s_out + tl * NF;          // stride 231 words -> 32 distinct banks
        switch (g) {                            // warp-uniform, no divergence
            case 0: do_feats<0>(x, srow); break;
            case 1: do_feats<1>(x, srow); break;
            case 2: do_feats<2>(x, srow); break;
            case 3: do_feats<3>(x, srow); break;
            case 4: do_feats<4>(x, srow); break;
            case 5: do_feats<5>(x, srow); break;
            case 6: do_feats<6>(x, srow); break;
            default: do_feats<7>(x, srow); break;
        }
    }
    __syncthreads();

    // Drain via TMA bulk copy WITH an evict-first L2 policy:
    //  - cp.async.bulk reads smem through the async proxy -> removes the
    //    LDS + STG wavefront streams (464 of 776 L1 cycles/CTA) from the LSU pipe.
    //  - L2::cache_hint evict_first reproduces __stcs's streaming semantics
    //    (the plain bulk copy's write-allocate thrashing of L2 is what sank R5's bench).
    // Tile is a flat run of valid*NF floats; src 16B-aligned, size mult of 16,
    // gdst 16B-aligned ((br*3996 + t0)*924 % 16 == 0).
    if (tid == 0) {
        float* gdst = out + ((size_t)br * NT_OUT + t0) * NF;
        uint32_t src    = smem_u32(s_out);
        uint32_t nbytes = (uint32_t)valid * (NF * 4);
        uint64_t pol;
        asm volatile("createpolicy.fractional.L2::evict_first.b64 %0, 1.0;" : "=l"(pol));
        asm volatile("fence.proxy.async.shared::cta;" ::: "memory");
        asm volatile("cp.async.bulk.global.shared::cta.bulk_group.L2::cache_hint"
                     " [%0], [%1], %2, %3;"
                     :: "l"(gdst), "r"(src), "r"(nbytes), "l"(pol) : "memory");
        asm volatile("cp.async.bulk.commit_group;" ::: "memory");
        asm volatile("cp.async.bulk.wait_group 0;" ::: "memory");
    }
    // Other warps exit immediately; 7 resident CTA slots keep 7 drains + computes
    // in flight per SM (cross-CTA pipeline).
}

extern "C" void kernel_launch(void* const* d_in, const int* in_sizes, int n_in,
                              void* d_out, int out_size) {
    const float* X   = (const float*)d_in[0];
    float*       out = (float*)d_out;

    const int br_total = in_sizes[0] / NT_IN;                 // 32
    dim3 grid((NT_OUT + TILE_T - 1) / TILE_T, br_total);      // 125 x 32 = 4000 blocks
    nvar_kernel<<<grid, NTHREADS>>>(X, out);
}